// round 17
// baseline (speedup 1.0000x reference)
#include <cuda_runtime.h>
#include <cuda_fp16.h>

// Problem constants (fixed by reference)
#define CN 64
#define HN 256
#define WN 256
#define L0N 1024   // g0 length (y samples), output innermost dim (j)
#define L1N 1024   // g1 length (x samples), output middle dim (i)
#define AC (-0.75f)

#define JT 128     // j-tile width per block
#define NB 256     // x0 bins
#define SROWH 136  // halves per smem row (272 B; 8B-aligned, odd 16B count)

// Precomputed y tap indices / weights
__device__ int4   g_yidx[L0N];
__device__ float4 g_ywt [L0N];
// x samples sorted by x0 bin: binstart + packed meta (w0,w1,w2,bitcast(i))
__device__ int    g_binstart[NB + 1];
__device__ float4 g_meta[L1N];

__device__ __forceinline__ void cubic_w(float t, float* w) {
    // Matches reference _cubic_weights exactly (A = -0.75)
    float t2 = t * t;
    float t3 = t2 * t;
    w[0] = AC * (t3 - 2.0f * t2 + t);
    w[1] = (AC + 2.0f) * t3 - (AC + 3.0f) * t2 + 1.0f;
    float s  = 1.0f - t;
    float s2 = s * s;
    w[2] = (AC + 2.0f) * s2 * s - (AC + 3.0f) * s2 + 1.0f;
    float u = 1.0f + s;
    w[3] = AC * (u * u * u) - 5.0f * AC * (u * u) + 8.0f * AC * u - 4.0f * AC;
}

// Single-block prep: y tables + counting sort of x samples (fast shfl scan).
__global__ void prep_kernel(const float* __restrict__ g0,
                            const float* __restrict__ g1) {
    __shared__ int sh_hist[NB];
    __shared__ int sh_wsum[8];
    __shared__ int sh_base[NB];
    const int tid  = threadIdx.x;   // 0..1023
    const int lane = tid & 31;

    // --- y taps ---
    {
        float x  = (g0[tid] + 1.0f) * 0.5f * (float)(HN - 1);
        float x0 = floorf(x);
        float t  = x - x0;
        int  i0  = (int)x0;
        float w[4];
        cubic_w(t, w);
        int idx[4];
#pragma unroll
        for (int b = 0; b < 4; b++) idx[b] = min(max(i0 - 1 + b, 0), HN - 1);
        g_yidx[tid] = make_int4(idx[0], idx[1], idx[2], idx[3]);
        g_ywt [tid] = make_float4(w[0], w[1], w[2], w[3]);
    }

    // --- x taps: bin by x0, counting sort ---
    float x  = (g1[tid] + 1.0f) * 0.5f * (float)(WN - 1);
    float x0 = floorf(x);
    float t  = x - x0;
    int bin  = min(max((int)x0, 0), NB - 1);
    float w[4];
    cubic_w(t, w);

    if (tid < NB) sh_hist[tid] = 0;
    __syncthreads();
    int rank = atomicAdd(&sh_hist[bin], 1);
    __syncthreads();

    // Two-level shfl scan over 256 bins (threads 0..255)
    if (tid < NB) {
        int v = sh_hist[tid];
        int inc = v;
#pragma unroll
        for (int off = 1; off < 32; off <<= 1) {
            int n = __shfl_up_sync(0xFFFFFFFF, inc, off);
            if (lane >= off) inc += n;
        }
        if (lane == 31) sh_wsum[tid >> 5] = inc;
        sh_base[tid] = inc - v;            // exclusive within warp
    }
    __syncthreads();
    if (tid < 8) {
        int v = sh_wsum[tid];
        int inc = v;
#pragma unroll
        for (int off = 1; off < 8; off <<= 1) {
            int n = __shfl_up_sync(0xFF, inc, off);
            if (tid >= off) inc += n;
        }
        sh_wsum[tid] = inc - v;            // exclusive warp offsets
    }
    __syncthreads();
    if (tid < NB) {
        int base = sh_base[tid] + sh_wsum[tid >> 5];
        sh_base[tid] = base;
        g_binstart[tid] = base;
        if (tid == NB - 1) g_binstart[NB] = base + sh_hist[tid];
    }
    __syncthreads();

    int pos = sh_base[bin] + rank;
    // w3 reconstructed in-kernel as 1 - w0 - w1 - w2 (partition of unity;
    // validated in an earlier round: rel_err stayed ~3.8e-7)
    g_meta[pos] = make_float4(w[0], w[1], w[2], __int_as_float(tid));
}

// Fused kernel: one block = (c, 128-wide j tile). 512 threads, 3 blocks/SM,
// 68 KB fp16 smem, grid 512 blocks = ~1.15 waves.
// Phase A: warp w owns j-pairs p = 4w..4w+3 (j = 2p, 2p+1). Per x: 8 LDG.32
//          -> one half2 STS.32. Accumulate fp32, store fp16.
// Phase B: warp w sweeps bins [16w, 16w+16); 4 tap rows held as float4 regs,
//          rotation loads ONE LDS.64 (4 half-j's/lane) + 2 cvt per bin.
//          Per entry: 1 LDG.128 meta + 16 FFMA + 1 STG.128.
__global__ void __launch_bounds__(512, 3)
fused_kernel(const float* __restrict__ v, float* __restrict__ out) {
    extern __shared__ __half sYH[];        // [256][SROWH]

    const int tid  = threadIdx.x;
    const int lane = tid & 31;
    const int wid  = tid >> 5;             // 0..15
    const int jt = blockIdx.x * JT;        // j tile base
    const int c  = blockIdx.y;

    const float* vc = v + (size_t)c * (HN * WN);

    // ---- Phase A: y-interpolation into fp16 smem ----
#pragma unroll
    for (int jp = 0; jp < 4; jp++) {
        const int p  = (wid << 2) + jp;    // pair index 0..63
        const int jl = p << 1;             // first j of pair
        const int4   yiA = g_yidx[jt + jl];
        const float4 wyA = g_ywt [jt + jl];
        const int4   yiB = g_yidx[jt + jl + 1];
        const float4 wyB = g_ywt [jt + jl + 1];
        const float* rA0 = vc + yiA.x * WN;
        const float* rA1 = vc + yiA.y * WN;
        const float* rA2 = vc + yiA.z * WN;
        const float* rA3 = vc + yiA.w * WN;
        const float* rB0 = vc + yiB.x * WN;
        const float* rB1 = vc + yiB.y * WN;
        const float* rB2 = vc + yiB.z * WN;
        const float* rB3 = vc + yiB.w * WN;
#pragma unroll
        for (int xc = 0; xc < 8; xc++) {
            const int x = xc * 32 + lane;
            float accA = wyA.x * __ldg(rA0 + x) + wyA.y * __ldg(rA1 + x)
                       + wyA.z * __ldg(rA2 + x) + wyA.w * __ldg(rA3 + x);
            float accB = wyB.x * __ldg(rB0 + x) + wyB.y * __ldg(rB1 + x)
                       + wyB.z * __ldg(rB2 + x) + wyB.w * __ldg(rB3 + x);
            *(__half2*)(sYH + x * SROWH + jl) = __floats2half2_rn(accA, accB);
        }
    }
    __syncthreads();

    // ---- Phase B: 16 consecutive bins per warp, float4 register rotation ----
    float* outc = out + ((size_t)c * L1N) * L0N + jt + (lane << 2);
    const __half* srow = sYH + (lane << 2);

    // load row xx: 4 half j's -> float4 (2 cvt)
    #define LOADROW(xx, dst) do {                                        \
        const uint2 u_ = *(const uint2*)(srow + (size_t)(xx) * SROWH);   \
        const float2 f01_ = __half22float2(*(const __half2*)&u_.x);      \
        const float2 f23_ = __half22float2(*(const __half2*)&u_.y);      \
        (dst) = make_float4(f01_.x, f01_.y, f23_.x, f23_.y);             \
    } while (0)

    const int b0 = wid << 4;               // first bin: 16 bins per warp

    float4 a0, a1, a2;
    LOADROW(max(b0 - 1, 0), a0);
    LOADROW(b0, a1);
    LOADROW(b0 + 1, a2);

    int s = g_binstart[b0];

#pragma unroll
    for (int bb = 0; bb < 16; bb++) {
        const int b = b0 + bb;
        float4 a3;
        LOADROW(min(b + 2, WN - 1), a3);
        const int e = g_binstart[b + 1];

        int k = s;
        for (; k + 1 < e; k += 2) {
            const float4 mA = g_meta[k];
            const float4 mB = g_meta[k + 1];
            const int iA = __float_as_int(mA.w);
            const int iB = __float_as_int(mB.w);
            const float w3A = 1.0f - mA.x - mA.y - mA.z;
            const float w3B = 1.0f - mB.x - mB.y - mB.z;
            float4 accA, accB;
            accA.x = mA.x * a0.x + mA.y * a1.x + mA.z * a2.x + w3A * a3.x;
            accA.y = mA.x * a0.y + mA.y * a1.y + mA.z * a2.y + w3A * a3.y;
            accA.z = mA.x * a0.z + mA.y * a1.z + mA.z * a2.z + w3A * a3.z;
            accA.w = mA.x * a0.w + mA.y * a1.w + mA.z * a2.w + w3A * a3.w;
            accB.x = mB.x * a0.x + mB.y * a1.x + mB.z * a2.x + w3B * a3.x;
            accB.y = mB.x * a0.y + mB.y * a1.y + mB.z * a2.y + w3B * a3.y;
            accB.z = mB.x * a0.z + mB.y * a1.z + mB.z * a2.z + w3B * a3.z;
            accB.w = mB.x * a0.w + mB.y * a1.w + mB.z * a2.w + w3B * a3.w;
            *(float4*)(outc + (size_t)iA * L0N) = accA;
            *(float4*)(outc + (size_t)iB * L0N) = accB;
        }
        if (k < e) {
            const float4 m = g_meta[k];
            const int i = __float_as_int(m.w);
            const float w3 = 1.0f - m.x - m.y - m.z;
            float4 acc;
            acc.x = m.x * a0.x + m.y * a1.x + m.z * a2.x + w3 * a3.x;
            acc.y = m.x * a0.y + m.y * a1.y + m.z * a2.y + w3 * a3.y;
            acc.z = m.x * a0.z + m.y * a1.z + m.z * a2.z + w3 * a3.z;
            acc.w = m.x * a0.w + m.y * a1.w + m.z * a2.w + w3 * a3.w;
            *(float4*)(outc + (size_t)i * L0N) = acc;
        }
        s = e;
        a0 = a1; a1 = a2; a2 = a3;
    }
    #undef LOADROW
}

extern "C" void kernel_launch(void* const* d_in, const int* in_sizes, int n_in,
                              void* d_out, int out_size) {
    const float* values = (const float*)d_in[0];   // (1,64,256,256)
    const float* g0     = (const float*)d_in[1];   // (1024,)
    const float* g1     = (const float*)d_in[2];   // (1024,)
    float* out = (float*)d_out;                    // (1,64,1024,1024)

    static int smem_set = 0;
    const int smem_bytes = HN * SROWH * sizeof(__half);  // 256*136*2 = 69632
    if (!smem_set) {
        cudaFuncSetAttribute(fused_kernel,
                             cudaFuncAttributeMaxDynamicSharedMemorySize,
                             smem_bytes);
        smem_set = 1;
    }

    prep_kernel<<<1, 1024>>>(g0, g1);

    dim3 grid(L0N / JT, CN);               // (8, 64) = 512 blocks
    fused_kernel<<<grid, 512, smem_bytes>>>(values, out);
}